// round 9
// baseline (speedup 1.0000x reference)
#include <cuda_runtime.h>
#include <cuda_fp16.h>
#include <cstdint>

// ---------------------------------------------------------------------------
// net: conv3x3(3->10)+relu -> conv3x3(10->20)+relu -> FC(2880->500) ->
//      heaviside(>=0 -> 1 else 0) -> FC(500->10)
// B = 65536
//
// conv: scalar fp32 FFMA, r5-proven smem layout (pitch-14 sh1 = conflict-free).
// FC1: tensor cores (mma.sync fp16); |v| < 6e-4 recomputed in fp64 from
//      the fp16 hi+lo activation pair.
// ---------------------------------------------------------------------------

#define B_TOTAL 65536
#define KDIM 2880
#define NOUT 500
#define NPAD 512
#define FIX_CAP (1u*1024u*1024u)
#define T_FIX 6e-4f

__device__ __half        g_a0[(size_t)B_TOTAL * KDIM];   // fp16 activations (hi)
__device__ __half        g_a1[(size_t)B_TOTAL * KDIM];   // fp16 residual (lo)
__device__ __half        g_b0[(size_t)NPAD * KDIM];      // fp16 weights
__device__ unsigned char g_s[(size_t)B_TOTAL * NOUT];    // heaviside bytes
__device__ unsigned int  g_fix[FIX_CAP];                 // fixup worklist
__device__ unsigned int  g_nfix;

__device__ __forceinline__ uint32_t smem_u32(const void* p) {
    uint32_t a;
    asm("{ .reg .u64 t; cvta.to.shared.u64 t, %1; cvt.u32.u64 %0, t; }" : "=r"(a) : "l"(p));
    return a;
}
__device__ __forceinline__ void cp16(uint32_t dst, const void* src) {
    asm volatile("cp.async.cg.shared.global [%0], [%1], 16;" :: "r"(dst), "l"(src));
}
__device__ __forceinline__ void ldx4(uint32_t* r, uint32_t addr) {
    asm volatile("ldmatrix.sync.aligned.m8n8.x4.shared.b16 {%0,%1,%2,%3}, [%4];"
                 : "=r"(r[0]), "=r"(r[1]), "=r"(r[2]), "=r"(r[3]) : "r"(addr));
}
__device__ __forceinline__ void mma16816(float* c, const uint32_t* a,
                                         uint32_t b0, uint32_t b1) {
    asm volatile(
        "mma.sync.aligned.m16n8k16.row.col.f32.f16.f16.f32 "
        "{%0,%1,%2,%3}, {%4,%5,%6,%7}, {%8,%9}, {%0,%1,%2,%3};"
        : "+f"(c[0]), "+f"(c[1]), "+f"(c[2]), "+f"(c[3])
        : "r"(a[0]), "r"(a[1]), "r"(a[2]), "r"(a[3]), "r"(b0), "r"(b1));
}

// ---------------------------------------------------------------------------
// Kernel 0: weight fp16 conversion + counter reset
// ---------------------------------------------------------------------------
__global__ __launch_bounds__(256)
void prep_kernel(const float* __restrict__ W)
{
    const size_t idx = (size_t)blockIdx.x * 256 + threadIdx.x;
    if (idx == 0) g_nfix = 0;
    if (idx >= (size_t)NPAD * KDIM) return;
    const int n = (int)(idx / KDIM);
    const float w = (n < NOUT) ? W[(size_t)n * KDIM + (idx % KDIM)] : 0.f;
    g_b0[idx] = __float2half_rn(w);
}

// ---------------------------------------------------------------------------
// Kernel 1: fused conv1+relu+conv2+relu, 4 samples/CTA (r5 layout).
// conv1: 560 tasks (s x 10 oc x 14 oy), 1 oc x 14 ox each.
// conv2: 240 tasks (s x 5 ocg x 12 oy), 4 oc x 12 ox each.
// smem: sw1[270] sw2[1800] sx[4*768] sh1[4*1960] = 51928 B
// ---------------------------------------------------------------------------
#define CONV_SMEM (12982 * 4)

__global__ __launch_bounds__(256, 2)
void conv_fused_kernel(const float* __restrict__ x,
                       const float* __restrict__ w1, const float* __restrict__ b1,
                       const float* __restrict__ w2, const float* __restrict__ b2)
{
    extern __shared__ float sm[];
    float* sw1 = sm;            // 270
    float* sw2 = sm + 270;      // 1800
    float* sx  = sm + 2070;     // 4*768
    float* sh1 = sm + 5142;     // 4*1960  (pitch 14 -> conflict-free)

    const int tid = threadIdx.x;
    const size_t b0 = (size_t)blockIdx.x * 4;

    const float* xb = x + b0 * 768;
    #pragma unroll
    for (int i = 0; i < 12; ++i) sx[i * 256 + tid] = xb[i * 256 + tid];
    for (int i = tid; i < 270; i += 256)  sw1[i] = w1[i];
    for (int i = tid; i < 1800; i += 256) sw2[i] = w2[i];
    __syncthreads();

    // ---- conv1: 560 tasks, 1 oc x 14 ox each ----
    for (int t = tid; t < 560; t += 256) {
        const int s  = t / 140;
        const int r  = t % 140;
        const int oc = r / 14;
        const int oy = r % 14;

        float acc[14];
        const float bz = b1[oc];
        #pragma unroll
        for (int i = 0; i < 14; i++) acc[i] = bz;

        #pragma unroll
        for (int ic = 0; ic < 3; ic++) {
            const float* w = sw1 + oc * 27 + ic * 9;
            #pragma unroll
            for (int ky = 0; ky < 3; ky++) {
                const float* row = sx + s * 768 + ic * 256 + (oy + ky) * 16;
                const float wa = w[ky*3+0], wb = w[ky*3+1], wc = w[ky*3+2];
                #pragma unroll
                for (int ox = 0; ox < 14; ox++)
                    acc[ox] += wa * row[ox] + wb * row[ox+1] + wc * row[ox+2];
            }
        }
        float* o = sh1 + s * 1960 + oc * 196 + oy * 14;
        #pragma unroll
        for (int i = 0; i < 14; i++) o[i] = fmaxf(acc[i], 0.f);
    }
    __syncthreads();

    // ---- conv2: 240 tasks, 4 oc x 12 ox each ----
    if (tid < 240) {
        const int s   = tid / 60;
        const int r   = tid % 60;
        const int ocg = r / 12;
        const int oy  = r % 12;
        const int oc  = ocg * 4;

        float acc[4][12];
        #pragma unroll
        for (int j = 0; j < 4; j++) {
            const float bz = b2[oc + j];
            #pragma unroll
            for (int i = 0; i < 12; i++) acc[j][i] = bz;
        }

        #pragma unroll 2
        for (int ic = 0; ic < 10; ic++) {
            float wv[4][9];
            #pragma unroll
            for (int j = 0; j < 4; j++) {
                const float* w = sw2 + (oc + j) * 90 + ic * 9;
                #pragma unroll
                for (int q = 0; q < 9; q++) wv[j][q] = w[q];
            }
            const float* rbase = sh1 + s * 1960 + ic * 196 + oy * 14;
            #pragma unroll
            for (int ky = 0; ky < 3; ky++) {
                const float* row = rbase + ky * 14;
                #pragma unroll
                for (int ox = 0; ox < 12; ox++) {
                    const float x0 = row[ox], x1 = row[ox+1], x2 = row[ox+2];
                    #pragma unroll
                    for (int j = 0; j < 4; j++)
                        acc[j][ox] += wv[j][ky*3+0] * x0 + wv[j][ky*3+1] * x1
                                    + wv[j][ky*3+2] * x2;
                }
            }
        }

        const size_t sbase = (b0 + s) * KDIM + oc * 144 + oy * 12;
        #pragma unroll
        for (int j = 0; j < 4; j++) {
            float v[12];
            #pragma unroll
            for (int i = 0; i < 12; i++) v[i] = fmaxf(acc[j][i], 0.f);

            __half2 h0[6], h1[6];
            #pragma unroll
            for (int q = 0; q < 6; q++) {
                const __half hia = __float2half_rn(v[2*q]);
                const __half hib = __float2half_rn(v[2*q+1]);
                const __half loa = __float2half_rn(v[2*q]   - __half2float(hia));
                const __half lob = __float2half_rn(v[2*q+1] - __half2float(hib));
                h0[q] = __halves2half2(hia, hib);
                h1[q] = __halves2half2(loa, lob);
            }
            // 24B at 8B-aligned offset -> 3x uint2
            char* p0 = reinterpret_cast<char*>(g_a0 + sbase + j * 144);
            char* p1 = reinterpret_cast<char*>(g_a1 + sbase + j * 144);
            const uint2* s0 = reinterpret_cast<const uint2*>(h0);
            const uint2* s1 = reinterpret_cast<const uint2*>(h1);
            #pragma unroll
            for (int q = 0; q < 3; q++) {
                reinterpret_cast<uint2*>(p0)[q] = s0[q];
                reinterpret_cast<uint2*>(p1)[q] = s1[q];
            }
        }
    }
}

// ---------------------------------------------------------------------------
// Kernel 2: FC1 via mma.sync fp16, 128x128 tile, BK=32, 4-stage cp.async.
// Epilogue: signs staged in smem -> coalesced 4B global stores.
// ---------------------------------------------------------------------------
#define BK 32
#define PITCH 80
#define TILE_BYTES (128 * PITCH)      // 10240
#define STAGE_BYTES (2 * TILE_BYTES)  // 20480 : A, B
#define NSTAGE 4
#define FC1_SMEM (NSTAGE * STAGE_BYTES)
#define NITER (KDIM / BK)             // 90
#define SPITCH 144                    // sign staging pitch (bytes)

__device__ __forceinline__ void load_stage(uint32_t sb,
                                           const __half* ga,
                                           const __half* gb,
                                           int k0, int tid)
{
    const __half* srcs[2] = { ga + k0, gb + k0 };
    #pragma unroll
    for (int t = 0; t < 2; ++t) {
        #pragma unroll
        for (int h = 0; h < 2; ++h) {
            const int idx = h * 256 + tid;        // 0..511
            const int r = idx >> 2, c = idx & 3;
            cp16(sb + t * TILE_BYTES + r * PITCH + c * 16,
                 srcs[t] + (size_t)r * KDIM + c * 8);
        }
    }
}

__global__ __launch_bounds__(256, 2)
void fc1_mma_kernel(const float* __restrict__ bias, int m_base)
{
    extern __shared__ char smc[];
    const uint32_t smb = smem_u32(smc);
    const int tid  = threadIdx.x;
    const int lane = tid & 31;
    const int wid  = tid >> 5;
    const int n0 = blockIdx.x * 128;
    const int m0 = m_base + blockIdx.y * 128;

    const int m_off = (wid & 1) * 64;
    const int n_off = (wid >> 1) * 32;

    const __half* ga = g_a0 + (size_t)m0 * KDIM;
    const __half* gb = g_b0 + (size_t)n0 * KDIM;

    float acc[4][4][4];
    #pragma unroll
    for (int i = 0; i < 4; i++)
        #pragma unroll
        for (int j = 0; j < 4; j++)
            #pragma unroll
            for (int q = 0; q < 4; q++) acc[i][j][q] = 0.f;

    #pragma unroll
    for (int p = 0; p < 3; ++p) {
        load_stage(smb + p * STAGE_BYTES, ga, gb, p * BK, tid);
        asm volatile("cp.async.commit_group;");
    }

    const uint32_t a_lane = (uint32_t)(lane & 15) * PITCH + (uint32_t)(lane >> 4) * 16;
    const uint32_t b_lane = (uint32_t)(lane & 7) * PITCH + (uint32_t)(lane >> 3) * 16;

    for (int i = 0; i < NITER; ++i) {
        asm volatile("cp.async.wait_group 2;");
        __syncthreads();
        if (i + 3 < NITER)
            load_stage(smb + ((i + 3) & 3) * STAGE_BYTES,
                       ga, gb, (i + 3) * BK, tid);
        asm volatile("cp.async.commit_group;");

        const uint32_t sb = smb + (i & 3) * STAGE_BYTES;
        const uint32_t Ab = sb;
        const uint32_t Bb = sb + TILE_BYTES;

        uint32_t bf[4][4];
        #pragma unroll
        for (int nt = 0; nt < 4; ++nt)
            ldx4(bf[nt], Bb + (uint32_t)(n_off + nt * 8) * PITCH + b_lane);

        #pragma unroll
        for (int kk = 0; kk < 2; ++kk) {
            uint32_t af[4][4];
            #pragma unroll
            for (int mt = 0; mt < 4; ++mt)
                ldx4(af[mt], Ab + (uint32_t)(m_off + mt * 16) * PITCH + a_lane
                             + (uint32_t)kk * 32);
            #pragma unroll
            for (int mt = 0; mt < 4; ++mt)
                #pragma unroll
                for (int nt = 0; nt < 4; ++nt)
                    mma16816(acc[mt][nt], af[mt], bf[nt][kk*2], bf[nt][kk*2+1]);
        }
    }

    // ---- epilogue: bias + heaviside -> smem staging, flag near-zeros ----
    __syncthreads();
    unsigned char* sbyte = reinterpret_cast<unsigned char*>(smc);

    const int g  = lane >> 2;
    const int t2 = (lane & 3) * 2;
    #pragma unroll
    for (int mt = 0; mt < 4; ++mt) {
        const int mlA = m_off + mt * 16 + g;
        const int mlB = mlA + 8;
        #pragma unroll
        for (int nt = 0; nt < 4; ++nt) {
            const int nl = n_off + nt * 8 + t2;
            const int n  = n0 + nl;
            if (n >= NOUT) continue;
            const float bn0 = __ldg(&bias[n]);
            const float bn1 = __ldg(&bias[n + 1]);

            const float vA0 = acc[mt][nt][0] + bn0;
            const float vA1 = acc[mt][nt][1] + bn1;
            const float vB0 = acc[mt][nt][2] + bn0;
            const float vB1 = acc[mt][nt][3] + bn1;

            sbyte[mlA * SPITCH + nl]     = vA0 >= 0.f;
            sbyte[mlA * SPITCH + nl + 1] = vA1 >= 0.f;
            sbyte[mlB * SPITCH + nl]     = vB0 >= 0.f;
            sbyte[mlB * SPITCH + nl + 1] = vB1 >= 0.f;

            const int mA = m0 + mlA, mB = m0 + mlB;
            if (fabsf(vA0) < T_FIX) {
                unsigned int ix = atomicAdd(&g_nfix, 1u);
                if (ix < FIX_CAP) g_fix[ix] = ((unsigned int)mA << 9) | (unsigned int)n;
            }
            if (fabsf(vA1) < T_FIX) {
                unsigned int ix = atomicAdd(&g_nfix, 1u);
                if (ix < FIX_CAP) g_fix[ix] = ((unsigned int)mA << 9) | (unsigned int)(n+1);
            }
            if (fabsf(vB0) < T_FIX) {
                unsigned int ix = atomicAdd(&g_nfix, 1u);
                if (ix < FIX_CAP) g_fix[ix] = ((unsigned int)mB << 9) | (unsigned int)n;
            }
            if (fabsf(vB1) < T_FIX) {
                unsigned int ix = atomicAdd(&g_nfix, 1u);
                if (ix < FIX_CAP) g_fix[ix] = ((unsigned int)mB << 9) | (unsigned int)(n+1);
            }
        }
    }
    __syncthreads();

    const int ncols  = (n0 + 128 <= NOUT) ? 128 : (NOUT - n0);
    const int nwords = ncols >> 2;
    #pragma unroll
    for (int it = 0; it < 16; ++it) {
        const int idx = it * 256 + tid;
        const int r = idx >> 5, w = idx & 31;
        if (w < nwords) {
            const uint32_t val = *reinterpret_cast<uint32_t*>(sbyte + r * SPITCH + w * 4);
            *reinterpret_cast<uint32_t*>(g_s + (size_t)(m0 + r) * NOUT + n0 + w * 4) = val;
        }
    }
}

// ---------------------------------------------------------------------------
// Kernel 3: fp64 recompute of flagged near-zero dots (warp per entry)
// ---------------------------------------------------------------------------
__global__ __launch_bounds__(256)
void fixup_kernel(const float* __restrict__ W, const float* __restrict__ bias)
{
    const int lane = threadIdx.x & 31;
    const int warp = threadIdx.x >> 5;
    unsigned int total = g_nfix;
    if (total > FIX_CAP) total = FIX_CAP;

    for (unsigned int e = blockIdx.x * 8 + warp; e < total; e += gridDim.x * 8) {
        const unsigned int ent = g_fix[e];
        const int m = (int)(ent >> 9);
        const int n = (int)(ent & 511u);
        const __half* h0 = g_a0 + (size_t)m * KDIM;
        const __half* h1 = g_a1 + (size_t)m * KDIM;
        const float* wr = W + (size_t)n * KDIM;
        double acc = 0.0;
        #pragma unroll 5
        for (int k = lane; k < KDIM; k += 32) {
            const double h = (double)__half2float(h0[k]) + (double)__half2float(h1[k]);
            acc += h * (double)wr[k];
        }
        #pragma unroll
        for (int off = 16; off > 0; off >>= 1)
            acc += __shfl_down_sync(0xffffffffu, acc, off);
        if (lane == 0) {
            const double v = acc + (double)bias[n];
            g_s[(size_t)m * NOUT + n] = (v >= 0.0) ? 1 : 0;
        }
    }
}

// ---------------------------------------------------------------------------
// Kernel 4: FC2 on binary signs, smem-staged, quad per sample
// ---------------------------------------------------------------------------
__global__ __launch_bounds__(256)
void fc2_kernel(const float* __restrict__ W2, const float* __restrict__ b2,
                float* __restrict__ out)
{
    __shared__ float sw[5000];                 // [10][500]
    __shared__ unsigned char ss[64 * 500];     // 64 sample rows

    const int tid = threadIdx.x;
    for (int i = tid; i < 5000; i += 256) sw[i] = W2[i];

    const size_t base = (size_t)blockIdx.x * 64;
    const uint4* gsrc = reinterpret_cast<const uint4*>(g_s + base * NOUT);
    uint4* sdst = reinterpret_cast<uint4*>(ss);
    #pragma unroll
    for (int i = 0; i < 8; ++i) {
        const int idx = i * 256 + tid;
        if (idx < 2000) sdst[idx] = gsrc[idx];
    }
    __syncthreads();

    const int s = tid >> 2;
    const int q = tid & 3;
    const unsigned char* srow = ss + s * NOUT + q * 125;
    const int nq = q * 125;

    float acc[10];
    #pragma unroll
    for (int i = 0; i < 10; i++) acc[i] = 0.f;

    for (int j = 0; j < 125; ++j) {
        const float sv = (float)srow[j];
        #pragma unroll
        for (int i = 0; i < 10; i++)
            acc[i] += sv * sw[i * NOUT + nq + j];
    }

    #pragma unroll
    for (int i = 0; i < 10; i++) {
        acc[i] += __shfl_xor_sync(0xffffffffu, acc[i], 1);
        acc[i] += __shfl_xor_sync(0xffffffffu, acc[i], 2);
    }

    if (q == 0) {
        float* o = out + (base + s) * 10;
        #pragma unroll
        for (int i = 0; i < 10; i++) o[i] = acc[i] + b2[i];
    }
}

// ---------------------------------------------------------------------------
extern "C" void kernel_launch(void* const* d_in, const int* in_sizes, int n_in,
                              void* d_out, int out_size)
{
    const float* x    = (const float*)d_in[0];
    const float* w1   = (const float*)d_in[1];
    const float* b1   = (const float*)d_in[2];
    const float* w2   = (const float*)d_in[3];
    const float* b2   = (const float*)d_in[4];
    const float* fcw  = (const float*)d_in[5];
    const float* fcb  = (const float*)d_in[6];
    const float* fc2w = (const float*)d_in[7];
    const float* fc2b = (const float*)d_in[8];

    cudaFuncSetAttribute(conv_fused_kernel,
                         cudaFuncAttributeMaxDynamicSharedMemorySize, CONV_SMEM);
    cudaFuncSetAttribute(fc1_mma_kernel,
                         cudaFuncAttributeMaxDynamicSharedMemorySize, FC1_SMEM);

    prep_kernel<<<(NPAD * KDIM + 255) / 256, 256>>>(fcw);
    conv_fused_kernel<<<B_TOTAL / 4, 256, CONV_SMEM>>>(x, w1, b1, w2, b2);

    dim3 g1(4, 256);
    fc1_mma_kernel<<<g1, 256, FC1_SMEM>>>(fcb, 0);
    fc1_mma_kernel<<<g1, 256, FC1_SMEM>>>(fcb, 32768);

    fixup_kernel<<<1024, 256>>>(fcw, fcb);
    fc2_kernel<<<B_TOTAL / 64, 256>>>(fc2w, fc2b, (float*)d_out);
}

// round 10
// speedup vs baseline: 2.1171x; 2.1171x over previous
#include <cuda_runtime.h>
#include <cuda_fp16.h>
#include <cstdint>

// ---------------------------------------------------------------------------
// net: conv3x3(3->10)+relu -> conv3x3(10->20)+relu -> FC(2880->500) ->
//      heaviside(>=0 -> 1 else 0) -> FC(500->10)
// B = 65536
//
// r5-proven configuration + coalesced fc1 sign stores.
// FC1 on tensor cores: single fp16 product; |v| < 6e-4 recomputed in fp64
// (only the SIGN survives the Heaviside).
// ---------------------------------------------------------------------------

#define B_TOTAL 65536
#define KDIM 2880
#define NOUT 500
#define NPAD 512
#define FIX_CAP (1u*1024u*1024u)
#define T_FIX 6e-4f

__device__ float         g_h2[(size_t)B_TOTAL * KDIM];   // fp32 activations
__device__ __half        g_a0[(size_t)B_TOTAL * KDIM];   // fp16 activations
__device__ __half        g_b0[(size_t)NPAD * KDIM];      // fp16 weights
__device__ unsigned char g_s[(size_t)B_TOTAL * NOUT];    // heaviside bytes
__device__ unsigned int  g_fix[FIX_CAP];                 // fixup worklist
__device__ unsigned int  g_nfix;

__device__ __forceinline__ uint32_t smem_u32(const void* p) {
    uint32_t a;
    asm("{ .reg .u64 t; cvta.to.shared.u64 t, %1; cvt.u32.u64 %0, t; }" : "=r"(a) : "l"(p));
    return a;
}
__device__ __forceinline__ void cp16(uint32_t dst, const void* src) {
    asm volatile("cp.async.cg.shared.global [%0], [%1], 16;" :: "r"(dst), "l"(src));
}
__device__ __forceinline__ void ldx4(uint32_t* r, uint32_t addr) {
    asm volatile("ldmatrix.sync.aligned.m8n8.x4.shared.b16 {%0,%1,%2,%3}, [%4];"
                 : "=r"(r[0]), "=r"(r[1]), "=r"(r[2]), "=r"(r[3]) : "r"(addr));
}
__device__ __forceinline__ void mma16816(float* c, const uint32_t* a,
                                         uint32_t b0, uint32_t b1) {
    asm volatile(
        "mma.sync.aligned.m16n8k16.row.col.f32.f16.f16.f32 "
        "{%0,%1,%2,%3}, {%4,%5,%6,%7}, {%8,%9}, {%0,%1,%2,%3};"
        : "+f"(c[0]), "+f"(c[1]), "+f"(c[2]), "+f"(c[3])
        : "r"(a[0]), "r"(a[1]), "r"(a[2]), "r"(a[3]), "r"(b0), "r"(b1));
}

// ---------------------------------------------------------------------------
// Kernel 0: weight fp16 conversion + counter reset
// ---------------------------------------------------------------------------
__global__ __launch_bounds__(256)
void prep_kernel(const float* __restrict__ W)
{
    const size_t idx = (size_t)blockIdx.x * 256 + threadIdx.x;
    if (idx == 0) g_nfix = 0;
    if (idx >= (size_t)NPAD * KDIM) return;
    const int n = (int)(idx / KDIM);
    const float w = (n < NOUT) ? W[(size_t)n * KDIM + (idx % KDIM)] : 0.f;
    g_b0[idx] = __float2half_rn(w);
}

// ---------------------------------------------------------------------------
// Kernel 1: fused conv1+relu+conv2+relu, 4 samples/CTA (r5 exact).
// ---------------------------------------------------------------------------
#define CONV_SMEM (12982 * 4)

__global__ __launch_bounds__(256, 2)
void conv_fused_kernel(const float* __restrict__ x,
                       const float* __restrict__ w1, const float* __restrict__ b1,
                       const float* __restrict__ w2, const float* __restrict__ b2)
{
    extern __shared__ float sm[];
    float* sw1 = sm;            // 270
    float* sw2 = sm + 270;      // 1800
    float* sx  = sm + 2070;     // 4*768
    float* sh1 = sm + 5142;     // 4*1960

    const int tid = threadIdx.x;
    const size_t b0 = (size_t)blockIdx.x * 4;

    const float* xb = x + b0 * 768;
    #pragma unroll
    for (int i = 0; i < 12; ++i) sx[i * 256 + tid] = xb[i * 256 + tid];
    for (int i = tid; i < 270; i += 256)  sw1[i] = w1[i];
    for (int i = tid; i < 1800; i += 256) sw2[i] = w2[i];
    __syncthreads();

    // ---- conv1: 280 tasks, 2 oc x 14 ox each ----
    for (int t = tid; t < 280; t += 256) {
        const int s   = t / 70;
        const int r   = t % 70;
        const int ocg = r / 14;
        const int oy  = r % 14;
        const int oc  = ocg * 2;

        float acc0[14], acc1[14];
        const float bz0 = b1[oc], bz1 = b1[oc + 1];
        #pragma unroll
        for (int i = 0; i < 14; i++) { acc0[i] = bz0; acc1[i] = bz1; }

        #pragma unroll
        for (int ic = 0; ic < 3; ic++) {
            const float* w0 = sw1 + oc * 27 + ic * 9;
            const float* w1p = w0 + 27;
            #pragma unroll
            for (int ky = 0; ky < 3; ky++) {
                const float* row = sx + s * 768 + ic * 256 + (oy + ky) * 16;
                const float wa0 = w0[ky*3+0], wb0 = w0[ky*3+1], wc0 = w0[ky*3+2];
                const float wa1 = w1p[ky*3+0], wb1 = w1p[ky*3+1], wc1 = w1p[ky*3+2];
                #pragma unroll
                for (int ox = 0; ox < 14; ox++) {
                    const float x0 = row[ox], x1 = row[ox+1], x2 = row[ox+2];
                    acc0[ox] += wa0 * x0 + wb0 * x1 + wc0 * x2;
                    acc1[ox] += wa1 * x0 + wb1 * x1 + wc1 * x2;
                }
            }
        }
        float* o0 = sh1 + s * 1960 + oc * 196 + oy * 14;
        float* o1 = o0 + 196;
        #pragma unroll
        for (int i = 0; i < 14; i++) {
            o0[i] = fmaxf(acc0[i], 0.f);
            o1[i] = fmaxf(acc1[i], 0.f);
        }
    }
    __syncthreads();

    // ---- conv2: 240 tasks, 4 oc x 12 ox each ----
    if (tid < 240) {
        const int s   = tid / 60;
        const int r   = tid % 60;
        const int ocg = r / 12;
        const int oy  = r % 12;
        const int oc  = ocg * 4;

        float acc[4][12];
        #pragma unroll
        for (int j = 0; j < 4; j++) {
            const float bz = b2[oc + j];
            #pragma unroll
            for (int i = 0; i < 12; i++) acc[j][i] = bz;
        }

        #pragma unroll 2
        for (int ic = 0; ic < 10; ic++) {
            float wv[4][9];
            #pragma unroll
            for (int j = 0; j < 4; j++) {
                const float* w = sw2 + (oc + j) * 90 + ic * 9;
                #pragma unroll
                for (int q = 0; q < 9; q++) wv[j][q] = w[q];
            }
            const float* rbase = sh1 + s * 1960 + ic * 196 + oy * 14;
            #pragma unroll
            for (int ky = 0; ky < 3; ky++) {
                const float* row = rbase + ky * 14;
                #pragma unroll
                for (int ox = 0; ox < 12; ox++) {
                    const float x0 = row[ox], x1 = row[ox+1], x2 = row[ox+2];
                    #pragma unroll
                    for (int j = 0; j < 4; j++)
                        acc[j][ox] += wv[j][ky*3+0] * x0 + wv[j][ky*3+1] * x1
                                    + wv[j][ky*3+2] * x2;
                }
            }
        }

        const size_t sbase = (b0 + s) * KDIM + oc * 144 + oy * 12;
        #pragma unroll
        for (int j = 0; j < 4; j++) {
            float v[12];
            #pragma unroll
            for (int i = 0; i < 12; i++) v[i] = fmaxf(acc[j][i], 0.f);

            float* outf = g_h2 + sbase + j * 144;
            #pragma unroll
            for (int q = 0; q < 3; q++)
                reinterpret_cast<float4*>(outf)[q] =
                    make_float4(v[q*4], v[q*4+1], v[q*4+2], v[q*4+3]);

            __half2* p0 = reinterpret_cast<__half2*>(g_a0 + sbase + j * 144);
            #pragma unroll
            for (int q = 0; q < 6; q++)
                p0[q] = __floats2half2_rn(v[2*q], v[2*q+1]);
        }
    }
}

// ---------------------------------------------------------------------------
// Kernel 2: FC1 via mma.sync fp16, 128x128 tile, BK=32, 3-stage cp.async.
// Epilogue: signs staged in smem -> coalesced 4B global stores.
// ---------------------------------------------------------------------------
#define BK 32
#define PITCH 80
#define TILE_BYTES (128 * PITCH)      // 10240
#define STAGE_BYTES (2 * TILE_BYTES)  // 20480 : A, B
#define NSTAGE 3
#define FC1_SMEM (NSTAGE * STAGE_BYTES)
#define SPITCH 144                    // sign staging pitch (bytes)

__device__ __forceinline__ void load_stage(uint32_t sb,
                                           const __half* ga,
                                           const __half* gb,
                                           int k0, int tid)
{
    const __half* srcs[2] = { ga + k0, gb + k0 };
    #pragma unroll
    for (int t = 0; t < 2; ++t) {
        #pragma unroll
        for (int h = 0; h < 2; ++h) {
            const int idx = h * 256 + tid;        // 0..511
            const int r = idx >> 2, c = idx & 3;
            cp16(sb + t * TILE_BYTES + r * PITCH + c * 16,
                 srcs[t] + (size_t)r * KDIM + c * 8);
        }
    }
}

__global__ __launch_bounds__(256, 2)
void fc1_mma_kernel(const float* __restrict__ bias)
{
    extern __shared__ char smc[];
    const uint32_t smb = smem_u32(smc);
    const int tid  = threadIdx.x;
    const int lane = tid & 31;
    const int wid  = tid >> 5;
    const int n0 = blockIdx.x * 128;
    const int m0 = blockIdx.y * 128;

    const int m_off = (wid & 1) * 64;
    const int n_off = (wid >> 1) * 32;

    const __half* ga = g_a0 + (size_t)m0 * KDIM;
    const __half* gb = g_b0 + (size_t)n0 * KDIM;

    float acc[4][4][4];
    #pragma unroll
    for (int i = 0; i < 4; i++)
        #pragma unroll
        for (int j = 0; j < 4; j++)
            #pragma unroll
            for (int q = 0; q < 4; q++) acc[i][j][q] = 0.f;

    load_stage(smb, ga, gb, 0, tid);
    asm volatile("cp.async.commit_group;");
    load_stage(smb + STAGE_BYTES, ga, gb, BK, tid);
    asm volatile("cp.async.commit_group;");

    const uint32_t a_lane = (uint32_t)(lane & 15) * PITCH + (uint32_t)(lane >> 4) * 16;
    const uint32_t b_lane = (uint32_t)(lane & 7) * PITCH + (uint32_t)(lane >> 3) * 16;

    for (int i = 0; i < KDIM / BK; ++i) {
        asm volatile("cp.async.wait_group 1;");
        __syncthreads();
        if (i + 2 < KDIM / BK)
            load_stage(smb + ((i + 2) % NSTAGE) * STAGE_BYTES,
                       ga, gb, (i + 2) * BK, tid);
        asm volatile("cp.async.commit_group;");

        const uint32_t sb = smb + (i % NSTAGE) * STAGE_BYTES;
        const uint32_t Ab = sb;
        const uint32_t Bb = sb + TILE_BYTES;

        uint32_t bf[4][4];
        #pragma unroll
        for (int nt = 0; nt < 4; ++nt)
            ldx4(bf[nt], Bb + (uint32_t)(n_off + nt * 8) * PITCH + b_lane);

        #pragma unroll
        for (int kk = 0; kk < 2; ++kk) {
            uint32_t af[4][4];
            #pragma unroll
            for (int mt = 0; mt < 4; ++mt)
                ldx4(af[mt], Ab + (uint32_t)(m_off + mt * 16) * PITCH + a_lane
                             + (uint32_t)kk * 32);
            #pragma unroll
            for (int mt = 0; mt < 4; ++mt)
                #pragma unroll
                for (int nt = 0; nt < 4; ++nt)
                    mma16816(acc[mt][nt], af[mt], bf[nt][kk*2], bf[nt][kk*2+1]);
        }
    }

    // ---- epilogue: bias + heaviside -> smem staging, flag near-zeros ----
    __syncthreads();   // all warps done with stage buffers
    unsigned char* sbyte = reinterpret_cast<unsigned char*>(smc);

    const int g  = lane >> 2;
    const int t2 = (lane & 3) * 2;
    #pragma unroll
    for (int mt = 0; mt < 4; ++mt) {
        const int mlA = m_off + mt * 16 + g;
        const int mlB = mlA + 8;
        #pragma unroll
        for (int nt = 0; nt < 4; ++nt) {
            const int nl = n_off + nt * 8 + t2;
            const int n  = n0 + nl;
            if (n >= NOUT) continue;
            const float bn0 = __ldg(&bias[n]);
            const float bn1 = __ldg(&bias[n + 1]);

            const float vA0 = acc[mt][nt][0] + bn0;
            const float vA1 = acc[mt][nt][1] + bn1;
            const float vB0 = acc[mt][nt][2] + bn0;
            const float vB1 = acc[mt][nt][3] + bn1;

            sbyte[mlA * SPITCH + nl]     = vA0 >= 0.f;
            sbyte[mlA * SPITCH + nl + 1] = vA1 >= 0.f;
            sbyte[mlB * SPITCH + nl]     = vB0 >= 0.f;
            sbyte[mlB * SPITCH + nl + 1] = vB1 >= 0.f;

            const int mA = m0 + mlA, mB = m0 + mlB;
            if (fabsf(vA0) < T_FIX) {
                unsigned int ix = atomicAdd(&g_nfix, 1u);
                if (ix < FIX_CAP) g_fix[ix] = ((unsigned int)mA << 9) | (unsigned int)n;
            }
            if (fabsf(vA1) < T_FIX) {
                unsigned int ix = atomicAdd(&g_nfix, 1u);
                if (ix < FIX_CAP) g_fix[ix] = ((unsigned int)mA << 9) | (unsigned int)(n+1);
            }
            if (fabsf(vB0) < T_FIX) {
                unsigned int ix = atomicAdd(&g_nfix, 1u);
                if (ix < FIX_CAP) g_fix[ix] = ((unsigned int)mB << 9) | (unsigned int)n;
            }
            if (fabsf(vB1) < T_FIX) {
                unsigned int ix = atomicAdd(&g_nfix, 1u);
                if (ix < FIX_CAP) g_fix[ix] = ((unsigned int)mB << 9) | (unsigned int)(n+1);
            }
        }
    }
    __syncthreads();

    // coalesced store: 128 rows x (up to 32) 4B words
    const int ncols  = (n0 + 128 <= NOUT) ? 128 : (NOUT - n0);   // 128 or 116
    const int nwords = ncols >> 2;                                // 32 or 29
    #pragma unroll
    for (int it = 0; it < 16; ++it) {
        const int idx = it * 256 + tid;
        const int r = idx >> 5, w = idx & 31;
        if (w < nwords) {
            const uint32_t val = *reinterpret_cast<uint32_t*>(sbyte + r * SPITCH + w * 4);
            *reinterpret_cast<uint32_t*>(g_s + (size_t)(m0 + r) * NOUT + n0 + w * 4) = val;
        }
    }
}

// ---------------------------------------------------------------------------
// Kernel 3: fp64 recompute of flagged near-zero dots (warp per entry)
// ---------------------------------------------------------------------------
__global__ __launch_bounds__(256)
void fixup_kernel(const float* __restrict__ W, const float* __restrict__ bias)
{
    const int lane = threadIdx.x & 31;
    const int warp = threadIdx.x >> 5;
    unsigned int total = g_nfix;
    if (total > FIX_CAP) total = FIX_CAP;

    for (unsigned int e = blockIdx.x * 8 + warp; e < total; e += gridDim.x * 8) {
        const unsigned int ent = g_fix[e];
        const int m = (int)(ent >> 9);
        const int n = (int)(ent & 511u);
        const float* hr = g_h2 + (size_t)m * KDIM;
        const float* wr = W + (size_t)n * KDIM;
        double acc = 0.0;
        #pragma unroll 5
        for (int k = lane; k < KDIM; k += 32)
            acc += (double)hr[k] * (double)wr[k];
        #pragma unroll
        for (int off = 16; off > 0; off >>= 1)
            acc += __shfl_down_sync(0xffffffffu, acc, off);
        if (lane == 0) {
            const double v = acc + (double)bias[n];
            g_s[(size_t)m * NOUT + n] = (v >= 0.0) ? 1 : 0;
        }
    }
}

// ---------------------------------------------------------------------------
// Kernel 4: FC2 on binary signs, smem-staged, quad per sample
// ---------------------------------------------------------------------------
__global__ __launch_bounds__(256)
void fc2_kernel(const float* __restrict__ W2, const float* __restrict__ b2,
                float* __restrict__ out)
{
    __shared__ float sw[5000];                 // [10][500]
    __shared__ unsigned char ss[64 * 500];     // 64 sample rows

    const int tid = threadIdx.x;
    for (int i = tid; i < 5000; i += 256) sw[i] = W2[i];

    const size_t base = (size_t)blockIdx.x * 64;
    const uint4* gsrc = reinterpret_cast<const uint4*>(g_s + base * NOUT);
    uint4* sdst = reinterpret_cast<uint4*>(ss);
    #pragma unroll
    for (int i = 0; i < 8; ++i) {
        const int idx = i * 256 + tid;
        if (idx < 2000) sdst[idx] = gsrc[idx];
    }
    __syncthreads();

    const int s = tid >> 2;
    const int q = tid & 3;
    const unsigned char* srow = ss + s * NOUT + q * 125;
    const int nq = q * 125;

    float acc[10];
    #pragma unroll
    for (int i = 0; i < 10; i++) acc[i] = 0.f;

    for (int j = 0; j < 125; ++j) {
        const float sv = (float)srow[j];
        #pragma unroll
        for (int i = 0; i < 10; i++)
            acc[i] += sv * sw[i * NOUT + nq + j];
    }

    #pragma unroll
    for (int i = 0; i < 10; i++) {
        acc[i] += __shfl_xor_sync(0xffffffffu, acc[i], 1);
        acc[i] += __shfl_xor_sync(0xffffffffu, acc[i], 2);
    }

    if (q == 0) {
        float* o = out + (base + s) * 10;
        #pragma unroll
        for (int i = 0; i < 10; i++) o[i] = acc[i] + b2[i];
    }
}

// ---------------------------------------------------------------------------
extern "C" void kernel_launch(void* const* d_in, const int* in_sizes, int n_in,
                              void* d_out, int out_size)
{
    const float* x    = (const float*)d_in[0];
    const float* w1   = (const float*)d_in[1];
    const float* b1   = (const float*)d_in[2];
    const float* w2   = (const float*)d_in[3];
    const float* b2   = (const float*)d_in[4];
    const float* fcw  = (const float*)d_in[5];
    const float* fcb  = (const float*)d_in[6];
    const float* fc2w = (const float*)d_in[7];
    const float* fc2b = (const float*)d_in[8];

    cudaFuncSetAttribute(conv_fused_kernel,
                         cudaFuncAttributeMaxDynamicSharedMemorySize, CONV_SMEM);
    cudaFuncSetAttribute(fc1_mma_kernel,
                         cudaFuncAttributeMaxDynamicSharedMemorySize, FC1_SMEM);

    prep_kernel<<<(NPAD * KDIM + 255) / 256, 256>>>(fcw);
    conv_fused_kernel<<<B_TOTAL / 4, 256, CONV_SMEM>>>(x, w1, b1, w2, b2);

    dim3 g1(4, 512);
    fc1_mma_kernel<<<g1, 256, FC1_SMEM>>>(fcb);

    fixup_kernel<<<1024, 256>>>(fcw, fcb);
    fc2_kernel<<<B_TOTAL / 64, 256>>>(fc2w, fc2b, (float*)d_out);
}

// round 11
// speedup vs baseline: 2.1211x; 1.0019x over previous
#include <cuda_runtime.h>
#include <cuda_fp16.h>
#include <cstdint>

// ---------------------------------------------------------------------------
// net: conv3x3(3->10)+relu -> conv3x3(10->20)+relu -> FC(2880->500) ->
//      heaviside(>=0 -> 1 else 0) -> FC(500->10)
// B = 65536
//
// conv1: scalar FFMA -> fp16 hi/lo planes in smem (channel-last).
// conv2: tensor-core GEMM (mma.sync fp16, 3-product hi/lo split, fp32 acc)
//        -> h2 exact to ~2e-9. No im2col: per-lane ldmatrix row addresses.
// FC1: tensor cores; |v| < 6e-4 recomputed in fp64 (only SIGN survives).
// ---------------------------------------------------------------------------

#define B_TOTAL 65536
#define KDIM 2880
#define NOUT 500
#define NPAD 512
#define FIX_CAP (1u*1024u*1024u)
#define T_FIX 6e-4f

__device__ float         g_h2[(size_t)B_TOTAL * KDIM];   // fp32 activations
__device__ __half        g_a0[(size_t)B_TOTAL * KDIM];   // fp16 activations
__device__ __half        g_b0[(size_t)NPAD * KDIM];      // fp16 weights
__device__ unsigned char g_s[(size_t)B_TOTAL * NOUT];    // heaviside bytes
__device__ unsigned int  g_fix[FIX_CAP];                 // fixup worklist
__device__ unsigned int  g_nfix;

__device__ __forceinline__ uint32_t smem_u32(const void* p) {
    uint32_t a;
    asm("{ .reg .u64 t; cvta.to.shared.u64 t, %1; cvt.u32.u64 %0, t; }" : "=r"(a) : "l"(p));
    return a;
}
__device__ __forceinline__ void cp16(uint32_t dst, const void* src) {
    asm volatile("cp.async.cg.shared.global [%0], [%1], 16;" :: "r"(dst), "l"(src));
}
__device__ __forceinline__ void ldx4(uint32_t* r, uint32_t addr) {
    asm volatile("ldmatrix.sync.aligned.m8n8.x4.shared.b16 {%0,%1,%2,%3}, [%4];"
                 : "=r"(r[0]), "=r"(r[1]), "=r"(r[2]), "=r"(r[3]) : "r"(addr));
}
__device__ __forceinline__ void ldx2(uint32_t* r, uint32_t addr) {
    asm volatile("ldmatrix.sync.aligned.m8n8.x2.shared.b16 {%0,%1}, [%2];"
                 : "=r"(r[0]), "=r"(r[1]) : "r"(addr));
}
__device__ __forceinline__ void mma16816(float* c, const uint32_t* a,
                                         uint32_t b0, uint32_t b1) {
    asm volatile(
        "mma.sync.aligned.m16n8k16.row.col.f32.f16.f16.f32 "
        "{%0,%1,%2,%3}, {%4,%5,%6,%7}, {%8,%9}, {%0,%1,%2,%3};"
        : "+f"(c[0]), "+f"(c[1]), "+f"(c[2]), "+f"(c[3])
        : "r"(a[0]), "r"(a[1]), "r"(a[2]), "r"(a[3]), "r"(b0), "r"(b1));
}

// ---------------------------------------------------------------------------
// Kernel 0: weight fp16 conversion + counter reset
// ---------------------------------------------------------------------------
__global__ __launch_bounds__(256)
void prep_kernel(const float* __restrict__ W)
{
    const size_t idx = (size_t)blockIdx.x * 256 + threadIdx.x;
    if (idx == 0) g_nfix = 0;
    if (idx >= (size_t)NPAD * KDIM) return;
    const int n = (int)(idx / KDIM);
    const float w = (n < NOUT) ? W[(size_t)n * KDIM + (idx % KDIM)] : 0.f;
    g_b0[idx] = __float2half_rn(w);
}

// ---------------------------------------------------------------------------
// Kernel 1: fused conv1 (FFMA) + conv2 (tensor cores), 4 samples/CTA.
//
// smem layout (bytes):
//   [0, 12288)        sx (4x768 fp32)  -- reused as epilogue stage (8 warps x 1536B)
//   [12288, 49920)    sh1hi: 4 samples x 196 pixels x pitch 24 halfs (16 used)
//   [49920, 87552)    sh1lo: same
//   [87552, 94848)    sb_hi: 24 oc x pitch 152 halfs (k = tap*16 + ic)
//   [94848, 102144)   sb_lo: same
//   [102144, 103224)  sw1 (270 fp32)
//   [103224, 103320)  sb2 (24 fp32)
// ---------------------------------------------------------------------------
#define SH1HI_OFF 12288
#define SH1LO_OFF 49920
#define SBHI_OFF  87552
#define SBLO_OFF  94848
#define SW1_OFF   102144
#define SB2_OFF   103224
#define CONV_SMEM 103424

__global__ __launch_bounds__(256, 2)
void conv_fused_kernel(const float* __restrict__ x,
                       const float* __restrict__ w1, const float* __restrict__ b1,
                       const float* __restrict__ w2, const float* __restrict__ b2)
{
    extern __shared__ char smc[];
    float*  sx    = reinterpret_cast<float*>(smc);
    __half* sh1hi = reinterpret_cast<__half*>(smc + SH1HI_OFF);
    __half* sh1lo = reinterpret_cast<__half*>(smc + SH1LO_OFF);
    __half* sbhi  = reinterpret_cast<__half*>(smc + SBHI_OFF);
    __half* sblo  = reinterpret_cast<__half*>(smc + SBLO_OFF);
    float*  sw1   = reinterpret_cast<float*>(smc + SW1_OFF);
    float*  sb2   = reinterpret_cast<float*>(smc + SB2_OFF);
    const uint32_t smb = smem_u32(smc);

    const int tid = threadIdx.x;
    const size_t b0 = (size_t)blockIdx.x * 4;

    // ---- phase 0: load inputs, zero h1/B planes ----
    const float* xb = x + b0 * 768;
    #pragma unroll
    for (int i = 0; i < 12; ++i) sx[i * 256 + tid] = xb[i * 256 + tid];
    for (int i = tid; i < 270; i += 256) sw1[i] = w1[i];
    if (tid < 24) sb2[tid] = (tid < 20) ? b2[tid] : 0.f;
    {
        uint4 zero4 = make_uint4(0, 0, 0, 0);
        uint4* z = reinterpret_cast<uint4*>(smc + SH1HI_OFF);
        for (int i = tid; i < 4704; i += 256) z[i] = zero4;   // both h1 planes (75264 B)
        uint4* zb = reinterpret_cast<uint4*>(smc + SBHI_OFF);
        for (int i = tid; i < 912; i += 256) zb[i] = zero4;   // both B planes (14592 B)
    }
    __syncthreads();

    // ---- phase 1: build B operand (w2 hi/lo) + conv1 -> sh1 hi/lo ----
    for (int t = tid; t < 1800; t += 256) {
        const int oc = t / 90, r = t % 90;
        const int ic = r / 9, ky = (r % 9) / 3, kx = r % 3;
        const float w = w2[t];
        const __half hi = __float2half_rn(w);
        const __half lo = __float2half_rn(w - __half2float(hi));
        const int col = (ky * 3 + kx) * 16 + ic;
        sbhi[oc * 152 + col] = hi;
        sblo[oc * 152 + col] = lo;
    }

    for (int t = tid; t < 560; t += 256) {
        const int s  = t / 140;
        const int r  = t % 140;
        const int oc = r / 14;
        const int oy = r % 14;

        float acc[14];
        const float bz = b1[oc];
        #pragma unroll
        for (int i = 0; i < 14; i++) acc[i] = bz;

        #pragma unroll
        for (int ic = 0; ic < 3; ic++) {
            const float* w = sw1 + oc * 27 + ic * 9;
            #pragma unroll
            for (int ky = 0; ky < 3; ky++) {
                const float* row = sx + s * 768 + ic * 256 + (oy + ky) * 16;
                const float wa = w[ky*3+0], wb = w[ky*3+1], wc = w[ky*3+2];
                #pragma unroll
                for (int ox = 0; ox < 14; ox++)
                    acc[ox] += wa * row[ox] + wb * row[ox+1] + wc * row[ox+2];
            }
        }
        const int pixbase = (s * 196 + oy * 14) * 24 + oc;
        #pragma unroll
        for (int ox = 0; ox < 14; ox++) {
            const float v  = fmaxf(acc[ox], 0.f);
            const __half hi = __float2half_rn(v);
            const __half lo = __float2half_rn(v - __half2float(hi));
            sh1hi[pixbase + ox * 24] = hi;
            sh1lo[pixbase + ox * 24] = lo;
        }
    }
    __syncthreads();

    // ---- phase 2: conv2 as GEMM, M=576 (36 m-tiles), N=24, K=9 taps x 16 ----
    const int wid  = tid >> 5;
    const int lane = tid & 31;
    const int ar   = lane & 15;                     // A row within m-tile
    const uint32_t asel = (uint32_t)(lane >> 4) * 16;   // k-half byte select

    float* stage = sx + wid * 384;   // 16 px x 24 oc fp32, per-warp (reuses sx)

    for (int mt = wid; mt < 36; mt += 8) {
        __syncwarp();

        float acc[3][4];
        #pragma unroll
        for (int nt = 0; nt < 3; nt++)
            #pragma unroll
            for (int q = 0; q < 4; q++) acc[nt][q] = 0.f;

        // per-lane base pixel for this m-tile
        const int p  = mt * 16 + ar;
        const int s  = p / 144;
        const int pp = p - s * 144;
        const int oy = pp / 12;
        const int ox = pp - oy * 12;
        const uint32_t abase = smb + SH1HI_OFF
                             + (uint32_t)(s * 196 + oy * 14 + ox) * 48 + asel;
        const uint32_t bbase = smb + SBHI_OFF
                             + (uint32_t)(lane & 7) * 304
                             + (uint32_t)((lane >> 3) & 1) * 16;

        #pragma unroll
        for (int kb = 0; kb < 9; ++kb) {
            const int ky = kb / 3, kx = kb - ky * 3;
            const uint32_t ahiaddr = abase + (uint32_t)(ky * 14 + kx) * 48;

            uint32_t ahi[4], alo[4];
            ldx4(ahi, ahiaddr);
            ldx4(alo, ahiaddr + (SH1LO_OFF - SH1HI_OFF));

            #pragma unroll
            for (int nt = 0; nt < 3; ++nt) {
                const uint32_t baddr = bbase + (uint32_t)nt * 2432 + (uint32_t)kb * 32;
                uint32_t bhi[2], blo[2];
                ldx2(bhi, baddr);
                ldx2(blo, baddr + (SBLO_OFF - SBHI_OFF));
                mma16816(acc[nt], ahi, bhi[0], bhi[1]);
                mma16816(acc[nt], ahi, blo[0], blo[1]);
                mma16816(acc[nt], alo, bhi[0], bhi[1]);
            }
        }

        // stage fragments: [p16][oc] fp32 with bias + relu
        const int g  = lane >> 2;
        const int c2 = (lane & 3) * 2;
        #pragma unroll
        for (int nt = 0; nt < 3; ++nt) {
            const int oc0 = nt * 8 + c2;
            stage[g * 24 + oc0]           = fmaxf(acc[nt][0] + sb2[oc0], 0.f);
            stage[g * 24 + oc0 + 1]       = fmaxf(acc[nt][1] + sb2[oc0 + 1], 0.f);
            stage[(g + 8) * 24 + oc0]     = fmaxf(acc[nt][2] + sb2[oc0], 0.f);
            stage[(g + 8) * 24 + oc0 + 1] = fmaxf(acc[nt][3] + sb2[oc0 + 1], 0.f);
        }
        __syncwarp();

        // write out oc < 20: 320 values = 10 iters x 32 lanes
        #pragma unroll
        for (int i = 0; i < 10; ++i) {
            const int idx = i * 32 + lane;
            const int oc  = idx >> 4;
            const int p16 = idx & 15;
            const float v = stage[p16 * 24 + oc];
            const int pg  = mt * 16 + p16;
            const int sg  = pg / 144;
            const int ppg = pg - sg * 144;
            const size_t off = (b0 + sg) * (size_t)KDIM + oc * 144 + ppg;
            g_h2[off] = v;
            g_a0[off] = __float2half_rn(v);
        }
    }
}

// ---------------------------------------------------------------------------
// Kernel 2: FC1 via mma.sync fp16, 128x128 tile, BK=32, 3-stage cp.async.
// Epilogue: signs staged in smem -> coalesced 4B global stores.
// ---------------------------------------------------------------------------
#define BK 32
#define PITCH 80
#define TILE_BYTES (128 * PITCH)      // 10240
#define STAGE_BYTES (2 * TILE_BYTES)  // 20480 : A, B
#define NSTAGE 3
#define FC1_SMEM (NSTAGE * STAGE_BYTES)
#define SPITCH 144                    // sign staging pitch (bytes)

__device__ __forceinline__ void load_stage(uint32_t sb,
                                           const __half* ga,
                                           const __half* gb,
                                           int k0, int tid)
{
    const __half* srcs[2] = { ga + k0, gb + k0 };
    #pragma unroll
    for (int t = 0; t < 2; ++t) {
        #pragma unroll
        for (int h = 0; h < 2; ++h) {
            const int idx = h * 256 + tid;        // 0..511
            const int r = idx >> 2, c = idx & 3;
            cp16(sb + t * TILE_BYTES + r * PITCH + c * 16,
                 srcs[t] + (size_t)r * KDIM + c * 8);
        }
    }
}

__global__ __launch_bounds__(256, 2)
void fc1_mma_kernel(const float* __restrict__ bias)
{
    extern __shared__ char smc[];
    const uint32_t smb = smem_u32(smc);
    const int tid  = threadIdx.x;
    const int lane = tid & 31;
    const int wid  = tid >> 5;
    const int n0 = blockIdx.x * 128;
    const int m0 = blockIdx.y * 128;

    const int m_off = (wid & 1) * 64;
    const int n_off = (wid >> 1) * 32;

    const __half* ga = g_a0 + (size_t)m0 * KDIM;
    const __half* gb = g_b0 + (size_t)n0 * KDIM;

    float acc[4][4][4];
    #pragma unroll
    for (int i = 0; i < 4; i++)
        #pragma unroll
        for (int j = 0; j < 4; j++)
            #pragma unroll
            for (int q = 0; q < 4; q++) acc[i][j][q] = 0.f;

    load_stage(smb, ga, gb, 0, tid);
    asm volatile("cp.async.commit_group;");
    load_stage(smb + STAGE_BYTES, ga, gb, BK, tid);
    asm volatile("cp.async.commit_group;");

    const uint32_t a_lane = (uint32_t)(lane & 15) * PITCH + (uint32_t)(lane >> 4) * 16;
    const uint32_t b_lane = (uint32_t)(lane & 7) * PITCH + (uint32_t)(lane >> 3) * 16;

    for (int i = 0; i < KDIM / BK; ++i) {
        asm volatile("cp.async.wait_group 1;");
        __syncthreads();
        if (i + 2 < KDIM / BK)
            load_stage(smb + ((i + 2) % NSTAGE) * STAGE_BYTES,
                       ga, gb, (i + 2) * BK, tid);
        asm volatile("cp.async.commit_group;");

        const uint32_t sb = smb + (i % NSTAGE) * STAGE_BYTES;
        const uint32_t Ab = sb;
        const uint32_t Bb = sb + TILE_BYTES;

        uint32_t bf[4][4];
        #pragma unroll
        for (int nt = 0; nt < 4; ++nt)
            ldx4(bf[nt], Bb + (uint32_t)(n_off + nt * 8) * PITCH + b_lane);

        #pragma unroll
        for (int kk = 0; kk < 2; ++kk) {
            uint32_t af[4][4];
            #pragma unroll
            for (int mt = 0; mt < 4; ++mt)
                ldx4(af[mt], Ab + (uint32_t)(m_off + mt * 16) * PITCH + a_lane
                             + (uint32_t)kk * 32);
            #pragma unroll
            for (int mt = 0; mt < 4; ++mt)
                #pragma unroll
                for (int nt = 0; nt < 4; ++nt)
                    mma16816(acc[mt][nt], af[mt], bf[nt][kk*2], bf[nt][kk*2+1]);
        }
    }

    // ---- epilogue: bias + heaviside -> smem staging, flag near-zeros ----
    __syncthreads();
    unsigned char* sbyte = reinterpret_cast<unsigned char*>(smc);

    const int g  = lane >> 2;
    const int t2 = (lane & 3) * 2;
    #pragma unroll
    for (int mt = 0; mt < 4; ++mt) {
        const int mlA = m_off + mt * 16 + g;
        const int mlB = mlA + 8;
        #pragma unroll
        for (int nt = 0; nt < 4; ++nt) {
            const int nl = n_off + nt * 8 + t2;
            const int n  = n0 + nl;
            if (n >= NOUT) continue;
            const float bn0 = __ldg(&bias[n]);
            const float bn1 = __ldg(&bias[n + 1]);

            const float vA0 = acc[mt][nt][0] + bn0;
            const float vA1 = acc[mt][nt][1] + bn1;
            const float vB0 = acc[mt][nt][2] + bn0;
            const float vB1 = acc[mt][nt][3] + bn1;

            sbyte[mlA * SPITCH + nl]     = vA0 >= 0.f;
            sbyte[mlA * SPITCH + nl + 1] = vA1 >= 0.f;
            sbyte[mlB * SPITCH + nl]     = vB0 >= 0.f;
            sbyte[mlB * SPITCH + nl + 1] = vB1 >= 0.f;

            const int mA = m0 + mlA, mB = m0 + mlB;
            if (fabsf(vA0) < T_FIX) {
                unsigned int ix = atomicAdd(&g_nfix, 1u);
                if (ix < FIX_CAP) g_fix[ix] = ((unsigned int)mA << 9) | (unsigned int)n;
            }
            if (fabsf(vA1) < T_FIX) {
                unsigned int ix = atomicAdd(&g_nfix, 1u);
                if (ix < FIX_CAP) g_fix[ix] = ((unsigned int)mA << 9) | (unsigned int)(n+1);
            }
            if (fabsf(vB0) < T_FIX) {
                unsigned int ix = atomicAdd(&g_nfix, 1u);
                if (ix < FIX_CAP) g_fix[ix] = ((unsigned int)mB << 9) | (unsigned int)n;
            }
            if (fabsf(vB1) < T_FIX) {
                unsigned int ix = atomicAdd(&g_nfix, 1u);
                if (ix < FIX_CAP) g_fix[ix] = ((unsigned int)mB << 9) | (unsigned int)(n+1);
            }
        }
    }
    __syncthreads();

    const int ncols  = (n0 + 128 <= NOUT) ? 128 : (NOUT - n0);
    const int nwords = ncols >> 2;
    #pragma unroll
    for (int it = 0; it < 16; ++it) {
        const int idx = it * 256 + tid;
        const int r = idx >> 5, w = idx & 31;
        if (w < nwords) {
            const uint32_t val = *reinterpret_cast<uint32_t*>(sbyte + r * SPITCH + w * 4);
            *reinterpret_cast<uint32_t*>(g_s + (size_t)(m0 + r) * NOUT + n0 + w * 4) = val;
        }
    }
}

// ---------------------------------------------------------------------------
// Kernel 3: fp64 recompute of flagged near-zero dots (warp per entry)
// ---------------------------------------------------------------------------
__global__ __launch_bounds__(256)
void fixup_kernel(const float* __restrict__ W, const float* __restrict__ bias)
{
    const int lane = threadIdx.x & 31;
    const int warp = threadIdx.x >> 5;
    unsigned int total = g_nfix;
    if (total > FIX_CAP) total = FIX_CAP;

    for (unsigned int e = blockIdx.x * 8 + warp; e < total; e += gridDim.x * 8) {
        const unsigned int ent = g_fix[e];
        const int m = (int)(ent >> 9);
        const int n = (int)(ent & 511u);
        const float* hr = g_h2 + (size_t)m * KDIM;
        const float* wr = W + (size_t)n * KDIM;
        double acc = 0.0;
        #pragma unroll 5
        for (int k = lane; k < KDIM; k += 32)
            acc += (double)hr[k] * (double)wr[k];
        #pragma unroll
        for (int off = 16; off > 0; off >>= 1)
            acc += __shfl_down_sync(0xffffffffu, acc, off);
        if (lane == 0) {
            const double v = acc + (double)bias[n];
            g_s[(size_t)m * NOUT + n] = (v >= 0.0) ? 1 : 0;
        }
    }
}

// ---------------------------------------------------------------------------
// Kernel 4: FC2 on binary signs, smem-staged, quad per sample
// ---------------------------------------------------------------------------
__global__ __launch_bounds__(256)
void fc2_kernel(const float* __restrict__ W2, const float* __restrict__ b2,
                float* __restrict__ out)
{
    __shared__ float sw[5000];                 // [10][500]
    __shared__ unsigned char ss[64 * 500];     // 64 sample rows

    const int tid = threadIdx.x;
    for (int i = tid; i < 5000; i += 256) sw[i] = W2[i];

    const size_t base = (size_t)blockIdx.x * 64;
    const uint4* gsrc = reinterpret_cast<const uint4*>(g_s + base * NOUT);
    uint4* sdst = reinterpret_cast<uint4*>(ss);
    #pragma unroll
    for (int i = 0; i < 8; ++i) {
        const int idx = i * 256 + tid;
        if (idx < 2000) sdst[idx] = gsrc[idx];
    }
    __syncthreads();

    const int s = tid >> 2;
    const int q = tid & 3;
    const unsigned char* srow = ss + s * NOUT + q * 125;
    const int nq = q * 125;

    float acc[10];
    #pragma unroll
    for (int i = 0; i < 10; i++) acc[i] = 0.f;

    for (int j = 0; j < 125; ++j) {
        const float sv = (float)srow[j];
        #pragma unroll
        for (int i = 0; i < 10; i++)
            acc[i] += sv * sw[i * NOUT + nq + j];
    }

    #pragma unroll
    for (int i = 0; i < 10; i++) {
        acc[i] += __shfl_xor_sync(0xffffffffu, acc[i], 1);
        acc[i] += __shfl_xor_sync(0xffffffffu, acc[i], 2);
    }

    if (q == 0) {
        float* o = out + (base + s) * 10;
        #pragma unroll
        for (int i = 0; i < 10; i++) o[i] = acc[i] + b2[i];
    }
}

// ---------------------------------------------------------------------------
extern "C" void kernel_launch(void* const* d_in, const int* in_sizes, int n_in,
                              void* d_out, int out_size)
{
    const float* x    = (const float*)d_in[0];
    const float* w1   = (const float*)d_in[1];
    const float* b1   = (const float*)d_in[2];
    const float* w2   = (const float*)d_in[3];
    const float* b2   = (const float*)d_in[4];
    const float* fcw  = (const float*)d_in[5];
    const float* fcb  = (const float*)d_in[6];
    const float* fc2w = (const float*)d_in[7];
    const float* fc2b = (const float*)d_in[8];

    cudaFuncSetAttribute(conv_fused_kernel,
                         cudaFuncAttributeMaxDynamicSharedMemorySize, CONV_SMEM);
    cudaFuncSetAttribute(fc1_mma_kernel,
                         cudaFuncAttributeMaxDynamicSharedMemorySize, FC1_SMEM);

    prep_kernel<<<(NPAD * KDIM + 255) / 256, 256>>>(fcw);
    conv_fused_kernel<<<B_TOTAL / 4, 256, CONV_SMEM>>>(x, w1, b1, w2, b2);

    dim3 g1(4, 512);
    fc1_mma_kernel<<<g1, 256, FC1_SMEM>>>(fcb);

    fixup_kernel<<<1024, 256>>>(fcw, fcb);
    fc2_kernel<<<B_TOTAL / 64, 256>>>(fc2w, fc2b, (float*)d_out);
}